// round 8
// baseline (speedup 1.0000x reference)
#include <cuda_runtime.h>
#include <cstdint>

#define N_NODES 500000
#define N_EDGES 16000000

#define CHUNK   1024               // edges per pipeline stage
#define STAGES  5
#define THREADS 256
#define NCHUNKS (N_EDGES / CHUNK)  // 15625 exactly

// smem: [0,64) mbarriers (5 x 8B, padded), then 5 stages of
// {src[1024] int, dst[1024] int, w[1024] float} = 12KB each.
#define STAGE_BYTES (CHUNK * 12)
#define MBAR_OFF    0
#define DATA_OFF    64
#define SMEM_TOTAL  (DATA_OFF + STAGES * STAGE_BYTES)   // 61504

// Per-node gain: relu(v[n]) * type_params[type[n]].  2 MB, stays L2-hot.
__device__ float g_gain[N_NODES];

// ---------------------------------------------------------------------------
// PTX helpers (inlined)
// ---------------------------------------------------------------------------
__device__ __forceinline__ uint32_t smem_u32(const void* p) {
    return (uint32_t)__cvta_generic_to_shared(p);
}
__device__ __forceinline__ void mbar_init(uint32_t addr, uint32_t count) {
    asm volatile("mbarrier.init.shared.b64 [%0], %1;"
                 :: "r"(addr), "r"(count) : "memory");
}
__device__ __forceinline__ void mbar_expect_tx(uint32_t addr, uint32_t bytes) {
    asm volatile("mbarrier.arrive.expect_tx.shared.b64 _, [%0], %1;"
                 :: "r"(addr), "r"(bytes) : "memory");
}
__device__ __forceinline__ void mbar_wait(uint32_t addr, uint32_t parity) {
    asm volatile(
        "{\n\t"
        ".reg .pred P;\n\t"
        "WAIT_%=:\n\t"
        "mbarrier.try_wait.parity.acquire.cta.shared::cta.b64 P, [%0], %1, 0x989680;\n\t"
        "@!P bra WAIT_%=;\n\t"
        "}"
        :: "r"(addr), "r"(parity) : "memory");
}
__device__ __forceinline__ void bulk_g2s(uint32_t sdst, const void* gsrc,
                                         uint32_t bytes, uint32_t mbar) {
    asm volatile(
        "cp.async.bulk.shared::cluster.global.mbarrier::complete_tx::bytes "
        "[%0], [%1], %2, [%3];"
        :: "r"(sdst), "l"(gsrc), "r"(bytes), "r"(mbar) : "memory");
}

// ---------------------------------------------------------------------------
// Kernel A: node prep. g_gain[n] = relu(v)*tp[type], out[n] = -v + stim + Vrest
// ---------------------------------------------------------------------------
__global__ void node_prep(const float* __restrict__ voltage,
                          const float* __restrict__ stimulus,
                          const int*   __restrict__ ntype,      // int32 (JAX x64 off)
                          const float* __restrict__ v_rest,
                          const float* __restrict__ type_params,
                          float* __restrict__ out,
                          int n)
{
    int i = blockIdx.x * blockDim.x + threadIdx.x;
    if (i < n) {
        float v = voltage[i];
        float r = fmaxf(v, 0.0f);
        int t = ntype[i];                 // values in [0,64)
        g_gain[i] = r * __ldg(&type_params[t]);
        out[i] = -v + stimulus[i] + v_rest[i];
    }
}

// ---------------------------------------------------------------------------
// Kernel B: persistent pipelined edge scatter.
// Producer (thread 0): cp.async.bulk pulls 12KB edge chunks into SMEM via the
// TMA engine -> zero LSU lanes / zero L1tex wavefronts for the 192MB stream.
// Consumers: LDS.128 reads, L2-hit gather into g_gain, predicated no-return
// atomic (only ~50% of messages are nonzero).
// ---------------------------------------------------------------------------
__global__ void __launch_bounds__(THREADS) edge_scatter(
    const int*   __restrict__ src_g,
    const int*   __restrict__ dst_g,
    const float* __restrict__ w_g,
    float*       __restrict__ out)
{
    extern __shared__ char smem[];
    const uint32_t sbase = smem_u32(smem);
    const int tid = threadIdx.x;
    const int G = gridDim.x;

    // how many chunks this CTA owns (grid-stride over chunk index)
    int nmine = (NCHUNKS - blockIdx.x + G - 1) / G;

    if (tid == 0) {
        #pragma unroll
        for (int s = 0; s < STAGES; s++)
            mbar_init(sbase + MBAR_OFF + s * 8, 1);
    }
    __syncthreads();

    // prologue: fill the pipeline
    if (tid == 0) {
        int pre = nmine < STAGES ? nmine : STAGES;
        for (int s = 0; s < pre; s++) {
            long long c = (long long)blockIdx.x + (long long)s * G;
            uint32_t mb = sbase + MBAR_OFF + s * 8;
            uint32_t st = sbase + DATA_OFF + s * STAGE_BYTES;
            mbar_expect_tx(mb, STAGE_BYTES);
            bulk_g2s(st,        src_g + c * CHUNK, CHUNK * 4, mb);
            bulk_g2s(st + 4096, dst_g + c * CHUNK, CHUNK * 4, mb);
            bulk_g2s(st + 8192, w_g   + c * CHUNK, CHUNK * 4, mb);
        }
    }

    for (int k = 0; k < nmine; k++) {
        int s  = k % STAGES;
        int ph = (k / STAGES) & 1;
        uint32_t mb = sbase + MBAR_OFF + s * 8;
        char* st = smem + DATA_OFF + s * STAGE_BYTES;

        mbar_wait(mb, ph);

        // 4 edges per thread, contiguous -> LDS.128, conflict-free
        int4   sv = ((const int4*)  (st        ))[tid];
        int4   dv = ((const int4*)  (st + 4096))[tid];
        float4 wv = ((const float4*)(st + 8192))[tid];

        float m0 = wv.x * __ldg(&g_gain[sv.x]);
        float m1 = wv.y * __ldg(&g_gain[sv.y]);
        float m2 = wv.z * __ldg(&g_gain[sv.z]);
        float m3 = wv.w * __ldg(&g_gain[sv.w]);

        if (m0 != 0.0f) atomicAdd(&out[dv.x], m0);
        if (m1 != 0.0f) atomicAdd(&out[dv.y], m1);
        if (m2 != 0.0f) atomicAdd(&out[dv.z], m2);
        if (m3 != 0.0f) atomicAdd(&out[dv.w], m3);

        __syncthreads();   // all lanes done with stage s

        if (tid == 0 && k + STAGES < nmine) {
            long long c = (long long)blockIdx.x + (long long)(k + STAGES) * G;
            mbar_expect_tx(mb, STAGE_BYTES);
            uint32_t stu = sbase + DATA_OFF + s * STAGE_BYTES;
            bulk_g2s(stu,        src_g + c * CHUNK, CHUNK * 4, mb);
            bulk_g2s(stu + 4096, dst_g + c * CHUNK, CHUNK * 4, mb);
            bulk_g2s(stu + 8192, w_g   + c * CHUNK, CHUNK * 4, mb);
        }
    }
}

// ---------------------------------------------------------------------------
// Kernel C: out[n] = out[n] / tau[n]
// ---------------------------------------------------------------------------
__global__ void finalize(const float* __restrict__ tau,
                         float* __restrict__ out,
                         int n)
{
    int i = blockIdx.x * blockDim.x + threadIdx.x;
    if (i < n) {
        out[i] = out[i] / tau[i];
    }
}

// ---------------------------------------------------------------------------
// Launch
//   d_in: 0 voltage, 1 stimulus, 2 neuron_type(i32), 3 edge_index(i32 2xE),
//         4 w, 5 V_i_rest, 6 tau_i, 7 type_params
// ---------------------------------------------------------------------------
extern "C" void kernel_launch(void* const* d_in, const int* in_sizes, int n_in,
                              void* d_out, int out_size)
{
    const float* voltage = (const float*)d_in[0];
    const float* stim    = (const float*)d_in[1];
    const int*   ntype   = (const int*)d_in[2];
    const int*   eidx    = (const int*)d_in[3];
    const float* w       = (const float*)d_in[4];
    const float* vrest   = (const float*)d_in[5];
    const float* tau     = (const float*)d_in[6];
    const float* tparams = (const float*)d_in[7];
    float*       out     = (float*)d_out;

    const int n_nodes = N_NODES;
    const int n_edges = N_EDGES;

    cudaFuncSetAttribute(edge_scatter,
                         cudaFuncAttributeMaxDynamicSharedMemorySize,
                         SMEM_TOTAL);

    // Kernel A
    {
        int threads = 256;
        int blocks = (n_nodes + threads - 1) / threads;
        node_prep<<<blocks, threads>>>(voltage, stim, ntype, vrest, tparams,
                                       out, n_nodes);
    }

    // Kernel B: persistent, 3 CTAs/SM (60KB smem each)
    {
        int blocks = 148 * 3;
        edge_scatter<<<blocks, THREADS, SMEM_TOTAL>>>(
            eidx, eidx + n_edges, w, out);
    }

    // Kernel C
    {
        int threads = 256;
        int blocks = (n_nodes + threads - 1) / threads;
        finalize<<<blocks, threads>>>(tau, out, n_nodes);
    }
}

// round 9
// speedup vs baseline: 1.9173x; 1.9173x over previous
#include <cuda_runtime.h>
#include <cstdint>

#define N_NODES 500000
#define N_EDGES 16000000
#define BIT_WORDS 15625            // 500000 / 32 exactly
#define BIT_BYTES (BIT_WORDS * 4)  // 62500

// Per-node gain: relu(v[n]) * type_params[type[n]].  2 MB, stays L2-hot.
// ~50% of entries are exactly 0.0f (relu of N(0,1) voltage).
__device__ float    g_gain[N_NODES];
// 1 bit per node: g_gain[n] != 0.  62.5 KB -> fits in SMEM per block.
__device__ unsigned g_bits[BIT_WORDS];

// ---------------------------------------------------------------------------
// Kernel A: node prep. g_gain, zero-bitmap, out[n] = -v + stim + Vrest
// ---------------------------------------------------------------------------
__global__ void node_prep(const float* __restrict__ voltage,
                          const float* __restrict__ stimulus,
                          const int*   __restrict__ ntype,      // int32 (JAX x64 off)
                          const float* __restrict__ v_rest,
                          const float* __restrict__ type_params,
                          float* __restrict__ out,
                          int n)
{
    int i = blockIdx.x * blockDim.x + threadIdx.x;
    float g = 0.0f;
    if (i < n) {
        float v = voltage[i];
        float r = fmaxf(v, 0.0f);
        int t = ntype[i];                 // values in [0,64)
        g = r * __ldg(&type_params[t]);
        g_gain[i] = g;
        out[i] = -v + stimulus[i] + v_rest[i];
    }
    unsigned b = __ballot_sync(0xffffffffu, g != 0.0f);
    if ((threadIdx.x & 31) == 0 && i < n) {
        g_bits[i >> 5] = b;               // warp base i -> word i/32 (< BIT_WORDS)
    }
}

// ---------------------------------------------------------------------------
// Hard-predicated gather + scatter: when bit==0, NEITHER the gather load nor
// the atomic issues a memory transaction. Inline asm so ptxas cannot hoist
// the read-only load out of the predicate (it provably did in R7).
// ---------------------------------------------------------------------------
__device__ __forceinline__ void edge_op(int bit, const float* gaddr,
                                        float w, float* oaddr)
{
    asm volatile(
        "{\n\t"
        ".reg .pred p;\n\t"
        ".reg .f32  g, m;\n\t"
        "setp.ne.s32 p, %0, 0;\n\t"
        "mov.f32 g, 0f00000000;\n\t"
        "@p ld.global.nc.f32 g, [%1];\n\t"
        "mul.f32 m, g, %2;\n\t"
        "@p red.global.add.f32 [%3], m;\n\t"
        "}"
        :: "r"(bit), "l"(gaddr), "f"(w), "l"(oaddr) : "memory");
}

// ---------------------------------------------------------------------------
// Kernel B: persistent edge scatter with SMEM zero-bitmap and truly
// predicated gather + RED (see edge_op).
// ---------------------------------------------------------------------------
__global__ void __launch_bounds__(256) edge_scatter(
    const int4*   __restrict__ src4,   // edge_index row 0, int32 x4
    const int4*   __restrict__ dst4,   // edge_index row 1, int32 x4
    const float4* __restrict__ w4,
    float*        __restrict__ out,
    int n_groups)                      // N_EDGES / 4
{
    extern __shared__ unsigned sbits[];

    // Cooperative bitmap load (amortized over ~9K edge-group iters/warp).
    for (int j = threadIdx.x; j < BIT_WORDS; j += blockDim.x)
        sbits[j] = g_bits[j];
    __syncthreads();

    int stride = gridDim.x * blockDim.x;
    for (int i = blockIdx.x * blockDim.x + threadIdx.x; i < n_groups; i += stride) {
        // streamed data: evict-first, don't thrash L2-resident g_gain/out
        int4   s = __ldcs(&src4[i]);
        int4   d = __ldcs(&dst4[i]);
        float4 w = __ldcs(&w4[i]);

        int b0 = (sbits[s.x >> 5] >> (s.x & 31)) & 1;
        int b1 = (sbits[s.y >> 5] >> (s.y & 31)) & 1;
        int b2 = (sbits[s.z >> 5] >> (s.z & 31)) & 1;
        int b3 = (sbits[s.w >> 5] >> (s.w & 31)) & 1;

        edge_op(b0, &g_gain[s.x], w.x, &out[d.x]);
        edge_op(b1, &g_gain[s.y], w.y, &out[d.y]);
        edge_op(b2, &g_gain[s.z], w.z, &out[d.z]);
        edge_op(b3, &g_gain[s.w], w.w, &out[d.w]);
    }
}

// ---------------------------------------------------------------------------
// Kernel C: out[n] = out[n] / tau[n]
// ---------------------------------------------------------------------------
__global__ void finalize(const float* __restrict__ tau,
                         float* __restrict__ out,
                         int n)
{
    int i = blockIdx.x * blockDim.x + threadIdx.x;
    if (i < n) {
        out[i] = out[i] / tau[i];
    }
}

// ---------------------------------------------------------------------------
// Launch
//   d_in: 0 voltage, 1 stimulus, 2 neuron_type(i32), 3 edge_index(i32 2xE),
//         4 w, 5 V_i_rest, 6 tau_i, 7 type_params
// ---------------------------------------------------------------------------
extern "C" void kernel_launch(void* const* d_in, const int* in_sizes, int n_in,
                              void* d_out, int out_size)
{
    const float* voltage = (const float*)d_in[0];
    const float* stim    = (const float*)d_in[1];
    const int*   ntype   = (const int*)d_in[2];
    const int*   eidx    = (const int*)d_in[3];
    const float* w       = (const float*)d_in[4];
    const float* vrest   = (const float*)d_in[5];
    const float* tau     = (const float*)d_in[6];
    const float* tparams = (const float*)d_in[7];
    float*       out     = (float*)d_out;

    const int n_nodes = N_NODES;
    const int n_edges = N_EDGES;

    // Allow >48KB dynamic smem for the bitmap kernel (idempotent, host-side).
    cudaFuncSetAttribute(edge_scatter,
                         cudaFuncAttributeMaxDynamicSharedMemorySize,
                         BIT_BYTES);

    // Kernel A
    {
        int threads = 256;
        int blocks = (n_nodes + threads - 1) / threads;
        node_prep<<<blocks, threads>>>(voltage, stim, ntype, vrest, tparams,
                                       out, n_nodes);
    }

    // Kernel B: persistent, 3 blocks/SM (62.5KB smem each)
    {
        const int4*   src4 = (const int4*)(eidx);
        const int4*   dst4 = (const int4*)(eidx + n_edges);
        const float4* w4   = (const float4*)w;
        int n_groups = n_edges / 4;           // 4,000,000 (exact)
        int threads = 256;
        int blocks = 148 * 3;                 // persistent wave
        edge_scatter<<<blocks, threads, BIT_BYTES>>>(src4, dst4, w4, out,
                                                     n_groups);
    }

    // Kernel C
    {
        int threads = 256;
        int blocks = (n_nodes + threads - 1) / threads;
        finalize<<<blocks, threads>>>(tau, out, n_nodes);
    }
}